// round 7
// baseline (speedup 1.0000x reference)
#include <cuda_runtime.h>
#include <cuda_bf16.h>
#include <math.h>
#include <stdint.h>

#define T_TOTAL 8192
#define N_PER_B 1024
#define NCTX    512
#define DMODEL  256
#define HEADS   8
#define DHEAD   32
#define LAYERS  6
#define FFDIM   1024

typedef __nv_bfloat16 bf16;

// ---------------------------------------------------------------------------
// Scratch (device globals — no allocation allowed)
// ---------------------------------------------------------------------------
__device__ float g_zin[T_TOTAL * 10];
__device__ float g_qkv[T_TOTAL * 768];
__device__ float g_z  [T_TOTAL * DMODEL];
__device__ bf16  g_ahi[T_TOTAL * DMODEL];
__device__ bf16  g_alo[T_TOTAL * DMODEL];
__device__ bf16  g_fhi[T_TOTAL * FFDIM];
__device__ bf16  g_flo[T_TOTAL * FFDIM];
#define WT_TOTAL 4784128
__device__ bf16  g_wThi[WT_TOTAL];
__device__ bf16  g_wTlo[WT_TOTAL];

// ---------------------------------------------------------------------------
// PTX helpers (base-target features only: cp.async / ldmatrix / mma.sync)
// ---------------------------------------------------------------------------
__device__ __forceinline__ uint32_t smem_u32(const void* p) {
    uint32_t a;
    asm("{ .reg .u64 t; cvta.to.shared.u64 t, %1; cvt.u32.u64 %0, t; }"
        : "=r"(a) : "l"(p));
    return a;
}

__device__ __forceinline__ void cp16(uint32_t saddr, const void* g) {
    asm volatile("cp.async.cg.shared.global [%0], [%1], 16;"
                 :: "r"(saddr), "l"(g) : "memory");
}
__device__ __forceinline__ void cp_commit() {
    asm volatile("cp.async.commit_group;" ::: "memory");
}
__device__ __forceinline__ void cp_wait1() {
    asm volatile("cp.async.wait_group 1;" ::: "memory");
}
__device__ __forceinline__ void cp_wait0() {
    asm volatile("cp.async.wait_group 0;" ::: "memory");
}

__device__ __forceinline__ void ldm4(uint32_t* d, uint32_t addr) {
    asm volatile("ldmatrix.sync.aligned.m8n8.x4.shared.b16 {%0,%1,%2,%3}, [%4];"
        : "=r"(d[0]), "=r"(d[1]), "=r"(d[2]), "=r"(d[3]) : "r"(addr));
}

__device__ __forceinline__ void mma16816(float* c, const uint32_t* a,
                                         uint32_t b0, uint32_t b1) {
    asm volatile(
        "mma.sync.aligned.m16n8k16.row.col.f32.bf16.bf16.f32 "
        "{%0,%1,%2,%3}, {%4,%5,%6,%7}, {%8,%9}, {%0,%1,%2,%3};"
        : "+f"(c[0]), "+f"(c[1]), "+f"(c[2]), "+f"(c[3])
        : "r"(a[0]), "r"(a[1]), "r"(a[2]), "r"(a[3]), "r"(b0), "r"(b1));
}

// ---------------------------------------------------------------------------
// bf16 hi/lo split helpers
// ---------------------------------------------------------------------------
__device__ __forceinline__ unsigned pk(bf16 a, bf16 b) {
    unsigned short ua = *(unsigned short*)&a;
    unsigned short ub = *(unsigned short*)&b;
    return (unsigned)ua | ((unsigned)ub << 16);
}

__device__ __forceinline__ void store_bf16pair4(bf16* ph, bf16* pl, float4 v) {
    bf16 h0 = __float2bfloat16(v.x), h1 = __float2bfloat16(v.y);
    bf16 h2 = __float2bfloat16(v.z), h3 = __float2bfloat16(v.w);
    bf16 l0 = __float2bfloat16(v.x - __bfloat162float(h0));
    bf16 l1 = __float2bfloat16(v.y - __bfloat162float(h1));
    bf16 l2 = __float2bfloat16(v.z - __bfloat162float(h2));
    bf16 l3 = __float2bfloat16(v.w - __bfloat162float(h3));
    uint2 uh; uh.x = pk(h0, h1); uh.y = pk(h2, h3);
    uint2 ul; ul.x = pk(l0, l1); ul.y = pk(l2, l3);
    *(uint2*)ph = uh;
    *(uint2*)pl = ul;
}

__device__ __forceinline__ void store_bf16pair2(bf16* ph, bf16* pl, float a, float b) {
    bf16 h0 = __float2bfloat16(a), h1 = __float2bfloat16(b);
    bf16 l0 = __float2bfloat16(a - __bfloat162float(h0));
    bf16 l1 = __float2bfloat16(b - __bfloat162float(h1));
    *(unsigned*)ph = pk(h0, h1);
    *(unsigned*)pl = pk(l0, l1);
}

// ---------------------------------------------------------------------------
// Weight transpose + bf16 split:  W[K,N] fp32 -> WT[N,K] bf16 hi/lo
// ---------------------------------------------------------------------------
__global__ void transpose_split(const float* __restrict__ W,
                                bf16* __restrict__ oh, bf16* __restrict__ ol,
                                int K, int N) {
    __shared__ float t[32][33];
    int n0 = blockIdx.x * 32, k0 = blockIdx.y * 32;
    int tx = threadIdx.x, ty = threadIdx.y;
    #pragma unroll
    for (int i = 0; i < 4; i++)
        t[ty + i * 8][tx] = W[(size_t)(k0 + ty + i * 8) * N + n0 + tx];
    __syncthreads();
    #pragma unroll
    for (int i = 0; i < 4; i++) {
        float v = t[tx][ty + i * 8];
        bf16 h = __float2bfloat16(v);
        bf16 l = __float2bfloat16(v - __bfloat162float(h));
        size_t o = (size_t)(n0 + ty + i * 8) * K + k0 + tx;
        oh[o] = h; ol[o] = l;
    }
}

// ---------------------------------------------------------------------------
// Warp-MMA GEMM: C[8192 x N] = (Ahi+Alo)[8192 x K] @ (Bhi+Blo)[N x K]^T + bias
// 3-pass bf16 split (hi*hi + lo*hi + hi*lo), fp32 register accumulation.
// CTA tile BM x 128, BK=32, 8 warps as 2(m) x 4(n), warp tile (BM/2) x 32.
// Smem rows padded to 80B -> conflict-free ldmatrix. cp.async double-buffered.
// ---------------------------------------------------------------------------
template<int BM, int RELU, int RES, int OUTBF>
__global__ __launch_bounds__(256, 2) void gemm_mma(
    const bf16* __restrict__ Ahi, const bf16* __restrict__ Alo,
    const bf16* __restrict__ Bhi, const bf16* __restrict__ Blo,
    const float* __restrict__ bias,
    float* __restrict__ Cf, bf16* __restrict__ Chi, bf16* __restrict__ Clo,
    int N, int K)
{
    constexpr int MI = BM / 32;                 // m16 frags per warp
    constexpr int STAGE = (2 * BM + 256) * 80;  // bytes per stage
    constexpr int OAh = 0;
    constexpr int OAl = BM * 80;
    constexpr int OBh = 2 * BM * 80;
    constexpr int OBl = 2 * BM * 80 + 128 * 80;

    extern __shared__ char smem[];
    const int tid = threadIdx.x;
    const int wid = tid >> 5, lane = tid & 31;
    const int wm = wid & 1, wn = wid >> 1;
    const int bn = blockIdx.x * 128, bm = blockIdx.y * BM;
    const uint32_t sb = smem_u32(smem);

    float c[MI][4][4];
    #pragma unroll
    for (int i = 0; i < MI; i++)
        #pragma unroll
        for (int j = 0; j < 4; j++)
            #pragma unroll
            for (int q = 0; q < 4; q++) c[i][j][q] = 0.0f;

    // per-lane ldmatrix addressing
    const int r8 = lane & 7, g8 = lane >> 3;
    const int a_row = wm * (BM / 2) + (g8 & 1) * 8 + r8;
    const int a_kof = (g8 >> 1) * 16;           // bytes
    const int b_row = wn * 32 + (g8 >> 1) * 8 + r8;
    const int b_kof = (g8 & 1) * 16;

    auto load_stage = [&](int s, int buf) {
        const int k0 = s * 32;
        const uint32_t sbase = sb + buf * STAGE;
        #pragma unroll
        for (int i = tid; i < BM * 4; i += 256) {
            int r = i >> 2, cc = i & 3;
            size_t g = (size_t)(bm + r) * K + k0 + cc * 8;
            uint32_t so = sbase + r * 80 + cc * 16;
            cp16(so + OAh, Ahi + g);
            cp16(so + OAl, Alo + g);
        }
        #pragma unroll
        for (int i = tid; i < 512; i += 256) {
            int r = i >> 2, cc = i & 3;
            size_t g = (size_t)(bn + r) * K + k0 + cc * 8;
            uint32_t so = sbase + r * 80 + cc * 16;
            cp16(so + OBh, Bhi + g);
            cp16(so + OBl, Blo + g);
        }
        cp_commit();
    };

    const int S = K >> 5;
    load_stage(0, 0);
    for (int s = 0; s < S; s++) {
        if (s + 1 < S) { load_stage(s + 1, (s + 1) & 1); cp_wait1(); }
        else cp_wait0();
        __syncthreads();

        const uint32_t sbase = sb + (s & 1) * STAGE;
        #pragma unroll
        for (int ks = 0; ks < 2; ks++) {
            uint32_t a[MI][4], bh[2][4], bl[2][4];
            #pragma unroll
            for (int mi = 0; mi < MI; mi++)
                ldm4(a[mi], sbase + OAh + (uint32_t)(a_row + mi * 16) * 80 + ks * 32 + a_kof);
            #pragma unroll
            for (int nj = 0; nj < 2; nj++)
                ldm4(bh[nj], sbase + OBh + (uint32_t)(b_row + nj * 16) * 80 + ks * 32 + b_kof);
            // pass 1: Ahi * Bhi
            #pragma unroll
            for (int mi = 0; mi < MI; mi++)
                #pragma unroll
                for (int ni = 0; ni < 4; ni++)
                    mma16816(c[mi][ni], a[mi], bh[ni >> 1][(ni & 1) * 2], bh[ni >> 1][(ni & 1) * 2 + 1]);
            // pass 2: Ahi * Blo
            #pragma unroll
            for (int nj = 0; nj < 2; nj++)
                ldm4(bl[nj], sbase + OBl + (uint32_t)(b_row + nj * 16) * 80 + ks * 32 + b_kof);
            #pragma unroll
            for (int mi = 0; mi < MI; mi++)
                #pragma unroll
                for (int ni = 0; ni < 4; ni++)
                    mma16816(c[mi][ni], a[mi], bl[ni >> 1][(ni & 1) * 2], bl[ni >> 1][(ni & 1) * 2 + 1]);
            // pass 3: Alo * Bhi  (overwrite A frags)
            #pragma unroll
            for (int mi = 0; mi < MI; mi++)
                ldm4(a[mi], sbase + OAl + (uint32_t)(a_row + mi * 16) * 80 + ks * 32 + a_kof);
            #pragma unroll
            for (int mi = 0; mi < MI; mi++)
                #pragma unroll
                for (int ni = 0; ni < 4; ni++)
                    mma16816(c[mi][ni], a[mi], bh[ni >> 1][(ni & 1) * 2], bh[ni >> 1][(ni & 1) * 2 + 1]);
        }
        __syncthreads();
    }

    // Epilogue: direct stores; lanes 0-3 cover 8 consecutive floats (full sector)
    const int quad = lane >> 2, tc = lane & 3;
    #pragma unroll
    for (int mi = 0; mi < MI; mi++) {
        #pragma unroll
        for (int ni = 0; ni < 4; ni++) {
            int row0 = bm + wm * (BM / 2) + mi * 16 + quad;
            int col = bn + wn * 32 + ni * 8 + tc * 2;
            float b0 = bias[col], b1 = bias[col + 1];
            float v00 = c[mi][ni][0] + b0, v01 = c[mi][ni][1] + b1;
            float v10 = c[mi][ni][2] + b0, v11 = c[mi][ni][3] + b1;
            if (RELU) {
                v00 = fmaxf(v00, 0.0f); v01 = fmaxf(v01, 0.0f);
                v10 = fmaxf(v10, 0.0f); v11 = fmaxf(v11, 0.0f);
            }
            size_t o0 = (size_t)row0 * N + col;
            size_t o1 = o0 + (size_t)8 * N;
            if (OUTBF) {
                store_bf16pair2(Chi + o0, Clo + o0, v00, v01);
                store_bf16pair2(Chi + o1, Clo + o1, v10, v11);
            } else if (RES) {
                float2 z0 = *(float2*)(Cf + o0);
                float2 z1 = *(float2*)(Cf + o1);
                z0.x += v00; z0.y += v01; z1.x += v10; z1.y += v11;
                *(float2*)(Cf + o0) = z0;
                *(float2*)(Cf + o1) = z1;
            } else {
                float2 w0 = {v00, v01}, w1 = {v10, v11};
                *(float2*)(Cf + o0) = w0;
                *(float2*)(Cf + o1) = w1;
            }
        }
    }
}

// ---------------------------------------------------------------------------
// Build encoder input features: [x(8), y(1), flag(1)] per token
// ---------------------------------------------------------------------------
__global__ void build_zin_kernel(const float* __restrict__ xc,
                                 const float* __restrict__ yc,
                                 const float* __restrict__ xt,
                                 float* __restrict__ zin) {
    int t = blockIdx.x * blockDim.x + threadIdx.x;
    if (t >= T_TOTAL) return;
    int b = t >> 10;
    int i = t & 1023;
    float* o = zin + (size_t)t * 10;
    if (i < NCTX) {
        const float* xp = xc + ((size_t)b * NCTX + i) * 8;
        #pragma unroll
        for (int j = 0; j < 8; j++) o[j] = xp[j];
        o[8] = yc[(size_t)b * NCTX + i];
        o[9] = 0.0f;
    } else {
        const float* xp = xt + ((size_t)b * NCTX + (i - NCTX)) * 8;
        #pragma unroll
        for (int j = 0; j < 8; j++) o[j] = xp[j];
        o[8] = 0.0f;
        o[9] = 1.0f;
    }
}

// ---------------------------------------------------------------------------
// enc1: fp32 SGEMM (K=10) with relu, outputs bf16 hi/lo pair.
// ---------------------------------------------------------------------------
__global__ __launch_bounds__(256) void enc1_kernel(
    const float* __restrict__ A, const float* __restrict__ B,
    const float* __restrict__ bias, bf16* __restrict__ Chi, bf16* __restrict__ Clo)
{
    const int BM = 128, BN = 64, BK = 16, N = DMODEL, K = 10;
    __shared__ float As[BK][BM + 1];
    __shared__ float Bs[BK][BN];
    int bm = blockIdx.y * BM;
    int bn = blockIdx.x * BN;
    int tid = threadIdx.x;
    int tx = tid & 15;
    int ty = tid >> 4;

    float acc[8][4];
    #pragma unroll
    for (int i = 0; i < 8; i++)
        #pragma unroll
        for (int j = 0; j < 4; j++) acc[i][j] = 0.0f;

    #pragma unroll
    for (int i = 0; i < 8; i++) {
        int idx = tid + i * 256;
        int m = idx >> 4, k = idx & 15;
        As[k][m] = (k < K) ? A[(size_t)(bm + m) * K + k] : 0.0f;
    }
    #pragma unroll
    for (int i = 0; i < 4; i++) {
        int idx = tid + i * 256;
        int k = idx >> 6, n = idx & 63;
        Bs[k][n] = (k < K) ? B[(size_t)k * N + bn + n] : 0.0f;
    }
    __syncthreads();
    #pragma unroll
    for (int k = 0; k < BK; k++) {
        float a[8];
        #pragma unroll
        for (int i = 0; i < 8; i++) a[i] = As[k][ty * 8 + i];
        float4 b4 = *(const float4*)&Bs[k][tx * 4];
        float b[4] = {b4.x, b4.y, b4.z, b4.w};
        #pragma unroll
        for (int i = 0; i < 8; i++)
            #pragma unroll
            for (int j = 0; j < 4; j++)
                acc[i][j] += a[i] * b[j];
    }

    #pragma unroll
    for (int i = 0; i < 8; i++) {
        int row = bm + ty * 8 + i;
        float4 v;
        v.x = fmaxf(acc[i][0] + bias[bn + tx * 4 + 0], 0.0f);
        v.y = fmaxf(acc[i][1] + bias[bn + tx * 4 + 1], 0.0f);
        v.z = fmaxf(acc[i][2] + bias[bn + tx * 4 + 2], 0.0f);
        v.w = fmaxf(acc[i][3] + bias[bn + tx * 4 + 3], 0.0f);
        size_t o = (size_t)row * N + bn + tx * 4;
        store_bf16pair4(Chi + o, Clo + o, v);
    }
}

// ---------------------------------------------------------------------------
// LayerNorm: warp per token, outputs bf16 hi/lo pair
// ---------------------------------------------------------------------------
__global__ __launch_bounds__(256) void ln_kernel(
    const float* __restrict__ z, const float* __restrict__ gamma,
    const float* __restrict__ beta, bf16* __restrict__ ohi, bf16* __restrict__ olo)
{
    int warp = threadIdx.x >> 5;
    int lane = threadIdx.x & 31;
    int t = blockIdx.x * 8 + warp;
    const float* zp = z + (size_t)t * DMODEL;

    float4 a = *(const float4*)(zp + lane * 4);
    float4 b = *(const float4*)(zp + 128 + lane * 4);
    float s  = a.x + a.y + a.z + a.w + b.x + b.y + b.z + b.w;
    float sq = a.x*a.x + a.y*a.y + a.z*a.z + a.w*a.w
             + b.x*b.x + b.y*b.y + b.z*b.z + b.w*b.w;
    #pragma unroll
    for (int o = 16; o > 0; o >>= 1) {
        s  += __shfl_xor_sync(0xffffffffu, s,  o);
        sq += __shfl_xor_sync(0xffffffffu, sq, o);
    }
    float mu = s * (1.0f / DMODEL);
    float var = sq * (1.0f / DMODEL) - mu * mu;
    float rs = rsqrtf(var + 1e-5f);

    float4 g0 = *(const float4*)(gamma + lane * 4);
    float4 g1 = *(const float4*)(gamma + 128 + lane * 4);
    float4 be0 = *(const float4*)(beta + lane * 4);
    float4 be1 = *(const float4*)(beta + 128 + lane * 4);
    float4 o0, o1;
    o0.x = (a.x - mu) * rs * g0.x + be0.x;
    o0.y = (a.y - mu) * rs * g0.y + be0.y;
    o0.z = (a.z - mu) * rs * g0.z + be0.z;
    o0.w = (a.w - mu) * rs * g0.w + be0.w;
    o1.x = (b.x - mu) * rs * g1.x + be1.x;
    o1.y = (b.y - mu) * rs * g1.y + be1.y;
    o1.z = (b.z - mu) * rs * g1.z + be1.z;
    o1.w = (b.w - mu) * rs * g1.w + be1.w;
    size_t base = (size_t)t * DMODEL;
    store_bf16pair4(ohi + base + lane * 4,       olo + base + lane * 4,       o0);
    store_bf16pair4(ohi + base + 128 + lane * 4, olo + base + 128 + lane * 4, o1);
}

// ---------------------------------------------------------------------------
// Fused masked attention (TNP-D), outputs bf16 hi/lo pair
// ---------------------------------------------------------------------------
__global__ __launch_bounds__(256) void attn_kernel(
    const float* __restrict__ qkv, bf16* __restrict__ ohi, bf16* __restrict__ olo)
{
    int b = blockIdx.z, h = blockIdx.y;
    int qrow = blockIdx.x * 256 + threadIdx.x;
    int token = b * N_PER_B + qrow;
    const float scale = 0.17677669529663689f;  // 1/sqrt(32)

    float q[DHEAD];
    const float* qp = qkv + (size_t)token * 768 + h * DHEAD;
    #pragma unroll
    for (int d = 0; d < DHEAD; d++) q[d] = qp[d] * scale;

    float mval = -1e30f, l = 0.0f;
    float acc[DHEAD];
    #pragma unroll
    for (int d = 0; d < DHEAD; d++) acc[d] = 0.0f;

    __shared__ float sK[128 * DHEAD];
    __shared__ float sV[128 * DHEAD];

    for (int c = 0; c < 4; c++) {
        __syncthreads();
        for (int i = threadIdx.x; i < 128 * DHEAD; i += 256) {
            int kk = i >> 5, d = i & 31;
            size_t kt = (size_t)(b * N_PER_B + c * 128 + kk) * 768;
            sK[i] = qkv[kt + 256 + h * DHEAD + d];
            sV[i] = qkv[kt + 512 + h * DHEAD + d];
        }
        __syncthreads();
        for (int j = 0; j < 128; j++) {
            const float* kp = sK + j * DHEAD;
            const float* vp = sV + j * DHEAD;
            float s = 0.0f;
            #pragma unroll
            for (int d = 0; d < DHEAD; d++) s += q[d] * kp[d];
            float nm = fmaxf(mval, s);
            float corr = __expf(mval - nm);
            float p = __expf(s - nm);
            l = l * corr + p;
            #pragma unroll
            for (int d = 0; d < DHEAD; d++) acc[d] = acc[d] * corr + p * vp[d];
            mval = nm;
        }
    }

    if (qrow >= NCTX) {
        const float* kp = qkv + (size_t)token * 768 + 256 + h * DHEAD;
        const float* vp = kp + 256;
        float s = 0.0f;
        #pragma unroll
        for (int d = 0; d < DHEAD; d++) s += q[d] * kp[d];
        float nm = fmaxf(mval, s);
        float corr = __expf(mval - nm);
        float p = __expf(s - nm);
        l = l * corr + p;
        #pragma unroll
        for (int d = 0; d < DHEAD; d++) acc[d] = acc[d] * corr + p * vp[d];
        mval = nm;
    }

    float inv = 1.0f / l;
    size_t base = (size_t)token * DMODEL + h * DHEAD;
    #pragma unroll
    for (int d = 0; d < DHEAD; d += 4) {
        float4 v;
        v.x = acc[d + 0] * inv; v.y = acc[d + 1] * inv;
        v.z = acc[d + 2] * inv; v.w = acc[d + 3] * inv;
        store_bf16pair4(ohi + base + d, olo + base + d, v);
    }
}

// ---------------------------------------------------------------------------
// Final copy z -> d_out
// ---------------------------------------------------------------------------
__global__ void copy_kernel(const float* __restrict__ src, float* __restrict__ dst) {
    int i = blockIdx.x * blockDim.x + threadIdx.x;
    ((float4*)dst)[i] = ((const float4*)src)[i];
}

// ---------------------------------------------------------------------------
// Launch
// ---------------------------------------------------------------------------
#define SMEM_BM128 81920   // (2*128+256)*80*2
#define SMEM_BM64  61440   // (2*64+256)*80*2

extern "C" void kernel_launch(void* const* d_in, const int* in_sizes, int n_in,
                              void* d_out, int out_size) {
    const float* xc     = (const float*)d_in[0];
    const float* yc     = (const float*)d_in[1];
    const float* xt     = (const float*)d_in[2];
    const float* enc_W1 = (const float*)d_in[3];
    const float* enc_b1 = (const float*)d_in[4];
    const float* enc_W2 = (const float*)d_in[5];
    const float* enc_b2 = (const float*)d_in[6];
    const float* Wqkv   = (const float*)d_in[7];
    const float* bqkv   = (const float*)d_in[8];
    const float* Wo     = (const float*)d_in[9];
    const float* bo     = (const float*)d_in[10];
    const float* ln1_g  = (const float*)d_in[11];
    const float* ln1_b  = (const float*)d_in[12];
    const float* ln2_g  = (const float*)d_in[13];
    const float* ln2_b  = (const float*)d_in[14];
    const float* Wff1   = (const float*)d_in[15];
    const float* bff1   = (const float*)d_in[16];
    const float* Wff2   = (const float*)d_in[17];
    const float* bff2   = (const float*)d_in[18];

    float *zin, *qkvb, *zb;
    bf16 *ahi, *alo, *fhi, *flo, *wThi, *wTlo;
    cudaGetSymbolAddress((void**)&zin,  g_zin);
    cudaGetSymbolAddress((void**)&qkvb, g_qkv);
    cudaGetSymbolAddress((void**)&zb,   g_z);
    cudaGetSymbolAddress((void**)&ahi,  g_ahi);
    cudaGetSymbolAddress((void**)&alo,  g_alo);
    cudaGetSymbolAddress((void**)&fhi,  g_fhi);
    cudaGetSymbolAddress((void**)&flo,  g_flo);
    cudaGetSymbolAddress((void**)&wThi, g_wThi);
    cudaGetSymbolAddress((void**)&wTlo, g_wTlo);

    cudaFuncSetAttribute(gemm_mma<128, 0, 0, 0>, cudaFuncAttributeMaxDynamicSharedMemorySize, SMEM_BM128);
    cudaFuncSetAttribute(gemm_mma<128, 1, 0, 1>, cudaFuncAttributeMaxDynamicSharedMemorySize, SMEM_BM128);
    cudaFuncSetAttribute(gemm_mma<64, 0, 0, 0>,  cudaFuncAttributeMaxDynamicSharedMemorySize, SMEM_BM64);
    cudaFuncSetAttribute(gemm_mma<64, 0, 1, 0>,  cudaFuncAttributeMaxDynamicSharedMemorySize, SMEM_BM64);

    dim3 tb(32, 8);

    // Weight transposes + bf16 split
    transpose_split<<<dim3(256 / 32, 256 / 32), tb>>>(enc_W2, wThi, wTlo, 256, 256);
    for (int l = 0; l < LAYERS; l++) {
        size_t base = 65536 + (size_t)l * 786432;
        transpose_split<<<dim3(768 / 32, 256 / 32), tb>>>(
            Wqkv + (size_t)l * 256 * 768, wThi + base, wTlo + base, 256, 768);
        transpose_split<<<dim3(256 / 32, 256 / 32), tb>>>(
            Wo + (size_t)l * 256 * 256, wThi + base + 196608, wTlo + base + 196608, 256, 256);
        transpose_split<<<dim3(1024 / 32, 256 / 32), tb>>>(
            Wff1 + (size_t)l * 256 * 1024, wThi + base + 262144, wTlo + base + 262144, 256, 1024);
        transpose_split<<<dim3(256 / 32, 1024 / 32), tb>>>(
            Wff2 + (size_t)l * 1024 * 256, wThi + base + 524288, wTlo + base + 524288, 1024, 256);
    }

    // Encoder
    build_zin_kernel<<<32, 256>>>(xc, yc, xt, zin);
    enc1_kernel<<<dim3(DMODEL / 64, T_TOTAL / 128), 256>>>(zin, enc_W1, enc_b1, ahi, alo);
    gemm_mma<64, 0, 0, 0><<<dim3(2, 128), 256, SMEM_BM64>>>(
        ahi, alo, wThi, wTlo, enc_b2, zb, nullptr, nullptr, 256, 256);

    // Transformer layers
    for (int l = 0; l < LAYERS; l++) {
        size_t base = 65536 + (size_t)l * 786432;
        ln_kernel<<<T_TOTAL / 8, 256>>>(zb, ln1_g + l * DMODEL, ln1_b + l * DMODEL, ahi, alo);
        gemm_mma<128, 0, 0, 0><<<dim3(6, 64), 256, SMEM_BM128>>>(
            ahi, alo, wThi + base, wTlo + base, bqkv + l * 768,
            qkvb, nullptr, nullptr, 768, 256);
        attn_kernel<<<dim3(4, HEADS, 8), 256>>>(qkvb, ahi, alo);
        gemm_mma<64, 0, 1, 0><<<dim3(2, 128), 256, SMEM_BM64>>>(
            ahi, alo, wThi + base + 196608, wTlo + base + 196608, bo + l * DMODEL,
            zb, nullptr, nullptr, 256, 256);
        ln_kernel<<<T_TOTAL / 8, 256>>>(zb, ln2_g + l * DMODEL, ln2_b + l * DMODEL, ahi, alo);
        gemm_mma<128, 1, 0, 1><<<dim3(8, 64), 256, SMEM_BM128>>>(
            ahi, alo, wThi + base + 262144, wTlo + base + 262144, bff1 + l * FFDIM,
            nullptr, fhi, flo, 1024, 256);
        gemm_mma<64, 0, 1, 0><<<dim3(2, 128), 256, SMEM_BM64>>>(
            fhi, flo, wThi + base + 524288, wTlo + base + 524288, bff2 + l * DMODEL,
            zb, nullptr, nullptr, 256, 1024);
    }

    copy_kernel<<<(T_TOTAL * DMODEL / 4) / 256, 256>>>(zb, (float*)d_out);
}

// round 11
// speedup vs baseline: 1.3993x; 1.3993x over previous
#include <cuda_runtime.h>
#include <cuda_bf16.h>
#include <math.h>
#include <stdint.h>

#define T_TOTAL 8192
#define N_PER_B 1024
#define NCTX    512
#define DMODEL  256
#define HEADS   8
#define DHEAD   32
#define LAYERS  6
#define FFDIM   1024

typedef __nv_bfloat16 bf16;

__device__ float g_zin[T_TOTAL * 10];
__device__ float g_z  [T_TOTAL * DMODEL];
__device__ bf16  g_ahi[T_TOTAL * DMODEL];
__device__ bf16  g_alo[T_TOTAL * DMODEL];
__device__ bf16  g_fhi[T_TOTAL * FFDIM];
__device__ bf16  g_flo[T_TOTAL * FFDIM];
__device__ bf16  g_qkvh[T_TOTAL * 768];
__device__ bf16  g_qkvl[T_TOTAL * 768];
__device__ bf16  g_vTh[8 * HEADS * DHEAD * N_PER_B];
__device__ bf16  g_vTl[8 * HEADS * DHEAD * N_PER_B];
#define WT_TOTAL 4784128
__device__ bf16  g_wThi[WT_TOTAL];
__device__ bf16  g_wTlo[WT_TOTAL];

// ---------------- PTX helpers ----------------
__device__ __forceinline__ uint32_t smem_u32(const void* p) {
    uint32_t a;
    asm("{ .reg .u64 t; cvta.to.shared.u64 t, %1; cvt.u32.u64 %0, t; }"
        : "=r"(a) : "l"(p));
    return a;
}
__device__ __forceinline__ void cp16(uint32_t saddr, const void* g) {
    asm volatile("cp.async.cg.shared.global [%0], [%1], 16;"
                 :: "r"(saddr), "l"(g) : "memory");
}
__device__ __forceinline__ void cp_commit() {
    asm volatile("cp.async.commit_group;" ::: "memory");
}
__device__ __forceinline__ void cp_wait1() {
    asm volatile("cp.async.wait_group 1;" ::: "memory");
}
__device__ __forceinline__ void cp_wait0() {
    asm volatile("cp.async.wait_group 0;" ::: "memory");
}
__device__ __forceinline__ void ldm4(uint32_t* d, uint32_t addr) {
    asm volatile("ldmatrix.sync.aligned.m8n8.x4.shared.b16 {%0,%1,%2,%3}, [%4];"
        : "=r"(d[0]), "=r"(d[1]), "=r"(d[2]), "=r"(d[3]) : "r"(addr));
}
__device__ __forceinline__ void mma16816(float* c, const uint32_t* a,
                                         uint32_t b0, uint32_t b1) {
    asm volatile(
        "mma.sync.aligned.m16n8k16.row.col.f32.bf16.bf16.f32 "
        "{%0,%1,%2,%3}, {%4,%5,%6,%7}, {%8,%9}, {%0,%1,%2,%3};"
        : "+f"(c[0]), "+f"(c[1]), "+f"(c[2]), "+f"(c[3])
        : "r"(a[0]), "r"(a[1]), "r"(a[2]), "r"(a[3]), "r"(b0), "r"(b1));
}

// ---------------- bf16 split helpers ----------------
__device__ __forceinline__ unsigned pk(bf16 a, bf16 b) {
    unsigned short ua = *(unsigned short*)&a;
    unsigned short ub = *(unsigned short*)&b;
    return (unsigned)ua | ((unsigned)ub << 16);
}
__device__ __forceinline__ void store_bf16pair4(bf16* ph, bf16* pl, float4 v) {
    bf16 h0 = __float2bfloat16(v.x), h1 = __float2bfloat16(v.y);
    bf16 h2 = __float2bfloat16(v.z), h3 = __float2bfloat16(v.w);
    uint2 uh; uh.x = pk(h0, h1); uh.y = pk(h2, h3);
    uint2 ul;
    ul.x = pk(__float2bfloat16(v.x - __bfloat162float(h0)),
              __float2bfloat16(v.y - __bfloat162float(h1)));
    ul.y = pk(__float2bfloat16(v.z - __bfloat162float(h2)),
              __float2bfloat16(v.w - __bfloat162float(h3)));
    *(uint2*)ph = uh;
    *(uint2*)pl = ul;
}
__device__ __forceinline__ void store_bf16pair2(bf16* ph, bf16* pl, float a, float b) {
    bf16 h0 = __float2bfloat16(a), h1 = __float2bfloat16(b);
    *(unsigned*)ph = pk(h0, h1);
    *(unsigned*)pl = pk(__float2bfloat16(a - __bfloat162float(h0)),
                        __float2bfloat16(b - __bfloat162float(h1)));
}

// ---------------- all weight transposes, ONE launch ----------------
__global__ void tr_all(const float* __restrict__ encW2,
                       const float* __restrict__ Wqkv, const float* __restrict__ Wo,
                       const float* __restrict__ Wff1, const float* __restrict__ Wff2,
                       bf16* __restrict__ oh, bf16* __restrict__ ol) {
    __shared__ float t[32][33];
    int z = blockIdx.z;
    const float* W; int K, N; size_t off;
    if (z == 0) { W = encW2; K = 256; N = 256; off = 0; }
    else {
        int l = (z - 1) >> 2, k = (z - 1) & 3;
        size_t base = 65536 + (size_t)l * 786432;
        if (k == 0)      { W = Wqkv + (size_t)l * 196608; K = 256;  N = 768;  off = base; }
        else if (k == 1) { W = Wo   + (size_t)l * 65536;  K = 256;  N = 256;  off = base + 196608; }
        else if (k == 2) { W = Wff1 + (size_t)l * 262144; K = 256;  N = 1024; off = base + 262144; }
        else             { W = Wff2 + (size_t)l * 262144; K = 1024; N = 256;  off = base + 524288; }
    }
    int n0 = blockIdx.x * 32, k0 = blockIdx.y * 32;
    if (n0 >= N || k0 >= K) return;
    int tx = threadIdx.x, ty = threadIdx.y;
    #pragma unroll
    for (int i = 0; i < 4; i++)
        t[ty + i * 8][tx] = W[(size_t)(k0 + ty + i * 8) * N + n0 + tx];
    __syncthreads();
    #pragma unroll
    for (int i = 0; i < 4; i++) {
        float v = t[tx][ty + i * 8];
        bf16 h = __float2bfloat16(v);
        size_t o = off + (size_t)(n0 + ty + i * 8) * K + k0 + tx;
        oh[o] = h;
        ol[o] = __float2bfloat16(v - __bfloat162float(h));
    }
}

// ---------------- warp-MMA GEMM (3-pass bf16 hi/lo) ----------------
template<int BM, int RELU, int RES, int OUTBF, int FIN>
__global__ __launch_bounds__(256, 2) void gemm_mma(
    const bf16* __restrict__ Ahi, const bf16* __restrict__ Alo,
    const bf16* __restrict__ Bhi, const bf16* __restrict__ Blo,
    const float* __restrict__ bias,
    float* __restrict__ Cf, bf16* __restrict__ Chi, bf16* __restrict__ Clo,
    float* __restrict__ Cout, int N, int K)
{
    constexpr int MI = BM / 32;
    constexpr int STAGE = (2 * BM + 256) * 80;
    constexpr int OAh = 0;
    constexpr int OAl = BM * 80;
    constexpr int OBh = 2 * BM * 80;
    constexpr int OBl = 2 * BM * 80 + 128 * 80;

    extern __shared__ char smem[];
    const int tid = threadIdx.x;
    const int wid = tid >> 5, lane = tid & 31;
    const int wm = wid & 1, wn = wid >> 1;
    const int bn = blockIdx.x * 128, bm = blockIdx.y * BM;
    const uint32_t sb = smem_u32(smem);

    float c[MI][4][4];
    #pragma unroll
    for (int i = 0; i < MI; i++)
        #pragma unroll
        for (int j = 0; j < 4; j++)
            #pragma unroll
            for (int q = 0; q < 4; q++) c[i][j][q] = 0.0f;

    const int r8 = lane & 7, g8 = lane >> 3;
    const int a_row = wm * (BM / 2) + (g8 & 1) * 8 + r8;
    const int a_kof = (g8 >> 1) * 16;
    const int b_row = wn * 32 + (g8 >> 1) * 8 + r8;
    const int b_kof = (g8 & 1) * 16;

    auto load_stage = [&](int s, int buf) {
        const int k0 = s * 32;
        const uint32_t sbase = sb + buf * STAGE;
        #pragma unroll
        for (int i = tid; i < BM * 4; i += 256) {
            int r = i >> 2, cc = i & 3;
            size_t g = (size_t)(bm + r) * K + k0 + cc * 8;
            uint32_t so = sbase + r * 80 + cc * 16;
            cp16(so + OAh, Ahi + g);
            cp16(so + OAl, Alo + g);
        }
        #pragma unroll
        for (int i = tid; i < 512; i += 256) {
            int r = i >> 2, cc = i & 3;
            size_t g = (size_t)(bn + r) * K + k0 + cc * 8;
            uint32_t so = sbase + r * 80 + cc * 16;
            cp16(so + OBh, Bhi + g);
            cp16(so + OBl, Blo + g);
        }
        cp_commit();
    };

    const int S = K >> 5;
    load_stage(0, 0);
    for (int s = 0; s < S; s++) {
        if (s + 1 < S) { load_stage(s + 1, (s + 1) & 1); cp_wait1(); }
        else cp_wait0();
        __syncthreads();

        const uint32_t sbase = sb + (s & 1) * STAGE;
        #pragma unroll
        for (int ks = 0; ks < 2; ks++) {
            uint32_t a[MI][4], bh[2][4], bl[2][4];
            #pragma unroll
            for (int mi = 0; mi < MI; mi++)
                ldm4(a[mi], sbase + OAh + (uint32_t)(a_row + mi * 16) * 80 + ks * 32 + a_kof);
            #pragma unroll
            for (int nj = 0; nj < 2; nj++)
                ldm4(bh[nj], sbase + OBh + (uint32_t)(b_row + nj * 16) * 80 + ks * 32 + b_kof);
            #pragma unroll
            for (int mi = 0; mi < MI; mi++)
                #pragma unroll
                for (int ni = 0; ni < 4; ni++)
                    mma16816(c[mi][ni], a[mi], bh[ni >> 1][(ni & 1) * 2], bh[ni >> 1][(ni & 1) * 2 + 1]);
            #pragma unroll
            for (int nj = 0; nj < 2; nj++)
                ldm4(bl[nj], sbase + OBl + (uint32_t)(b_row + nj * 16) * 80 + ks * 32 + b_kof);
            #pragma unroll
            for (int mi = 0; mi < MI; mi++)
                #pragma unroll
                for (int ni = 0; ni < 4; ni++)
                    mma16816(c[mi][ni], a[mi], bl[ni >> 1][(ni & 1) * 2], bl[ni >> 1][(ni & 1) * 2 + 1]);
            #pragma unroll
            for (int mi = 0; mi < MI; mi++)
                ldm4(a[mi], sbase + OAl + (uint32_t)(a_row + mi * 16) * 80 + ks * 32 + a_kof);
            #pragma unroll
            for (int mi = 0; mi < MI; mi++)
                #pragma unroll
                for (int ni = 0; ni < 4; ni++)
                    mma16816(c[mi][ni], a[mi], bh[ni >> 1][(ni & 1) * 2], bh[ni >> 1][(ni & 1) * 2 + 1]);
        }
        __syncthreads();
    }

    const int quad = lane >> 2, tc = lane & 3;
    #pragma unroll
    for (int mi = 0; mi < MI; mi++) {
        #pragma unroll
        for (int ni = 0; ni < 4; ni++) {
            int row0 = bm + wm * (BM / 2) + mi * 16 + quad;
            int col = bn + wn * 32 + ni * 8 + tc * 2;
            float b0 = bias[col], b1 = bias[col + 1];
            float v00 = c[mi][ni][0] + b0, v01 = c[mi][ni][1] + b1;
            float v10 = c[mi][ni][2] + b0, v11 = c[mi][ni][3] + b1;
            if (RELU) {
                v00 = fmaxf(v00, 0.0f); v01 = fmaxf(v01, 0.0f);
                v10 = fmaxf(v10, 0.0f); v11 = fmaxf(v11, 0.0f);
            }
            size_t o0 = (size_t)row0 * N + col;
            size_t o1 = o0 + (size_t)8 * N;
            if (OUTBF) {
                store_bf16pair2(Chi + o0, Clo + o0, v00, v01);
                store_bf16pair2(Chi + o1, Clo + o1, v10, v11);
            } else if (RES) {
                float2 z0 = *(float2*)(Cf + o0);
                float2 z1 = *(float2*)(Cf + o1);
                z0.x += v00; z0.y += v01; z1.x += v10; z1.y += v11;
                *(float2*)(Cf + o0) = z0;
                *(float2*)(Cf + o1) = z1;
                if (FIN) {
                    *(float2*)(Cout + o0) = z0;
                    *(float2*)(Cout + o1) = z1;
                }
            } else {
                float2 w0 = {v00, v01}, w1 = {v10, v11};
                *(float2*)(Cf + o0) = w0;
                *(float2*)(Cf + o1) = w1;
            }
        }
    }
}

// ---------------- V transpose: qkv V-section -> vT[(b,h,d)][token] ----------------
__global__ void vt_kernel(const bf16* __restrict__ qh, const bf16* __restrict__ ql,
                          bf16* __restrict__ vth, bf16* __restrict__ vtl) {
    __shared__ bf16 th[32][33], tl[32][33];
    int b = blockIdx.z, h = blockIdx.y, t0 = blockIdx.x * 32;
    int tx = threadIdx.x, ty = threadIdx.y;
    #pragma unroll
    for (int i = 0; i < 4; i++) {
        int tok = t0 + ty + i * 8;
        size_t g = (size_t)(b * N_PER_B + tok) * 768 + 512 + h * 32 + tx;
        th[ty + i * 8][tx] = qh[g];
        tl[ty + i * 8][tx] = ql[g];
    }
    __syncthreads();
    #pragma unroll
    for (int i = 0; i < 4; i++) {
        int d = ty + i * 8;
        size_t o = ((size_t)((b * 8 + h) * 32 + d)) * N_PER_B + t0 + tx;
        vth[o] = th[tx][d];
        vtl[o] = tl[tx][d];
    }
}

// ---------------- MMA flash attention, fixed-max softmax ----------------
#define ATT_SQH  0
#define ATT_SQL  10240
#define ATT_BUF0 20480
#define ATT_KH   0
#define ATT_KL   10240
#define ATT_VTH  20480
#define ATT_VTL  29184
#define ATT_BUFSZ 37888
#define ATT_OS   96256
#define ATT_LS   113152
#define ATT_SMEM 113664

__global__ __launch_bounds__(256) void attn_mma(
    const bf16* __restrict__ qh, const bf16* __restrict__ ql,
    const bf16* __restrict__ vth, const bf16* __restrict__ vtl,
    bf16* __restrict__ ohi, bf16* __restrict__ olo)
{
    extern __shared__ char smem[];
    const int tid = threadIdx.x, wid = tid >> 5, lane = tid & 31;
    const int qb = blockIdx.x, h = blockIdx.y, b = blockIdx.z;
    const uint32_t sb = smem_u32(smem);
    const float SC = 0.17677669529663689f;

    const int r8 = lane & 7, g8 = lane >> 3;

    // Q tile [128 x 32] hi/lo
    #pragma unroll
    for (int i = 0; i < 4; i++) {
        int idx = tid + i * 256;
        int st = idx >> 9, rem = idx & 511;
        int r = rem >> 2, cc = rem & 3;
        int token = b * N_PER_B + qb * 128 + r;
        const bf16* src = (st ? ql : qh) + (size_t)token * 768 + h * 32 + cc * 8;
        cp16(sb + (st ? ATT_SQL : ATT_SQH) + r * 80 + cc * 16, src);
    }
    auto load_kv = [&](int c, int buf) {
        uint32_t base = sb + ATT_BUF0 + buf * ATT_BUFSZ;
        #pragma unroll
        for (int i = 0; i < 4; i++) {
            int idx = tid + i * 256;
            int st = idx >> 9, rem = idx & 511;
            int r = rem >> 2, cc = rem & 3;
            int token = b * N_PER_B + c * 128 + r;
            const bf16* src = (st ? ql : qh) + (size_t)token * 768 + 256 + h * 32 + cc * 8;
            cp16(base + (st ? ATT_KL : ATT_KH) + r * 80 + cc * 16, src);
        }
        #pragma unroll
        for (int i = 0; i < 4; i++) {
            int idx = tid + i * 256;
            int st = idx >> 9, rem = idx & 511;
            int r = rem >> 4, cc = rem & 15;
            size_t g = ((size_t)((b * 8 + h) * 32 + r)) * N_PER_B + c * 128 + cc * 8;
            const bf16* src = (st ? vtl : vth) + g;
            cp16(base + (st ? ATT_VTL : ATT_VTH) + r * 272 + cc * 16, src);
        }
        cp_commit();
    };
    load_kv(0, 0);   // group0 = Q + KV0

    float co[4][4];
    #pragma unroll
    for (int i = 0; i < 4; i++)
        #pragma unroll
        for (int j = 0; j < 4; j++) co[i][j] = 0.0f;
    float l0 = 0.0f, l1 = 0.0f;
    uint32_t qfh[2][4], qfl[2][4];

    const int a_row = wid * 16 + (g8 & 1) * 8 + r8;
    const int a_kof = (g8 >> 1) * 16;
    const int b_r8 = (g8 >> 1) * 8 + r8;
    const int b_kof = (g8 & 1) * 16;

    for (int c = 0; c < 4; c++) {
        if (c < 3) { load_kv(c + 1, (c + 1) & 1); cp_wait1(); }
        else cp_wait0();
        __syncthreads();
        if (c == 0) {
            #pragma unroll
            for (int ks = 0; ks < 2; ks++) {
                ldm4(qfh[ks], sb + ATT_SQH + (uint32_t)a_row * 80 + ks * 32 + a_kof);
                ldm4(qfl[ks], sb + ATT_SQL + (uint32_t)a_row * 80 + ks * 32 + a_kof);
            }
        }
        const uint32_t kb = sb + ATT_BUF0 + (c & 1) * ATT_BUFSZ;

        // S[16 x 128] = Q Kt (3-pass)
        float cs[16][4];
        #pragma unroll
        for (int t = 0; t < 16; t++)
            #pragma unroll
            for (int q = 0; q < 4; q++) cs[t][q] = 0.0f;
        #pragma unroll
        for (int ks = 0; ks < 2; ks++) {
            #pragma unroll
            for (int nj = 0; nj < 8; nj++) {
                uint32_t kf[4];
                uint32_t ra = kb + ATT_KH + (uint32_t)(nj * 16 + b_r8) * 80 + ks * 32 + b_kof;
                ldm4(kf, ra);
                mma16816(cs[2 * nj],     qfh[ks], kf[0], kf[1]);
                mma16816(cs[2 * nj + 1], qfh[ks], kf[2], kf[3]);
                mma16816(cs[2 * nj],     qfl[ks], kf[0], kf[1]);
                mma16816(cs[2 * nj + 1], qfl[ks], kf[2], kf[3]);
                ldm4(kf, ra + (ATT_KL - ATT_KH));
                mma16816(cs[2 * nj],     qfh[ks], kf[0], kf[1]);
                mma16816(cs[2 * nj + 1], qfh[ks], kf[2], kf[3]);
            }
        }

        // P = exp(S*scale) (fixed max), split hi/lo
        uint32_t pph0[16], pph1[16], ppl0[16], ppl1[16];
        #pragma unroll
        for (int t = 0; t < 16; t++) {
            float p0 = __expf(fminf(cs[t][0] * SC, 70.0f));
            float p1 = __expf(fminf(cs[t][1] * SC, 70.0f));
            float p2 = __expf(fminf(cs[t][2] * SC, 70.0f));
            float p3 = __expf(fminf(cs[t][3] * SC, 70.0f));
            l0 += p0 + p1; l1 += p2 + p3;
            bf16 h0 = __float2bfloat16(p0), h1 = __float2bfloat16(p1);
            bf16 h2 = __float2bfloat16(p2), h3 = __float2bfloat16(p3);
            pph0[t] = pk(h0, h1);
            pph1[t] = pk(h2, h3);
            ppl0[t] = pk(__float2bfloat16(p0 - __bfloat162float(h0)),
                         __float2bfloat16(p1 - __bfloat162float(h1)));
            ppl1[t] = pk(__float2bfloat16(p2 - __bfloat162float(h2)),
                         __float2bfloat16(p3 - __bfloat162float(h3)));
        }

        // O += P * Vt (3-pass)
        #pragma unroll
        for (int j = 0; j < 8; j++) {
            uint32_t Ah[4] = {pph0[2 * j], pph1[2 * j], pph0[2 * j + 1], pph1[2 * j + 1]};
            uint32_t Al[4] = {ppl0[2 * j], ppl1[2 * j], ppl0[2 * j + 1], ppl1[2 * j + 1]};
            #pragma unroll
            for (int nv = 0; nv < 2; nv++) {
                uint32_t vf[4];
                uint32_t ra = kb + ATT_VTH + (uint32_t)(nv * 16 + b_r8) * 272 + j * 32 + b_kof;
                ldm4(vf, ra);
                mma16816(co[2 * nv],     Ah, vf[0], vf[1]);
                mma16816(co[2 * nv + 1], Ah, vf[2], vf[3]);
                mma16816(co[2 * nv],     Al, vf[0], vf[1]);
                mma16816(co[2 * nv + 1], Al, vf[2], vf[3]);
                ldm4(vf, ra + (ATT_VTL - ATT_VTH));
                mma16816(co[2 * nv],     Ah, vf[0], vf[1]);
                mma16816(co[2 * nv + 1], Ah, vf[2], vf[3]);
            }
        }
        __syncthreads();
    }

    l0 += __shfl_xor_sync(0xffffffffu, l0, 1);
    l0 += __shfl_xor_sync(0xffffffffu, l0, 2);
    l1 += __shfl_xor_sync(0xffffffffu, l1, 1);
    l1 += __shfl_xor_sync(0xffffffffu, l1, 2);
    {
        const int g = lane >> 2, tc = lane & 3;
        float* Os = (float*)(smem + ATT_OS);
        float* Ls = (float*)(smem + ATT_LS);
        int r0 = wid * 16 + g;
        if (tc == 0) { Ls[r0] = l0; Ls[r0 + 8] = l1; }
        #pragma unroll
        for (int ni = 0; ni < 4; ni++) {
            int d = ni * 8 + tc * 2;
            Os[r0 * 33 + d]           = co[ni][0];
            Os[r0 * 33 + d + 1]       = co[ni][1];
            Os[(r0 + 8) * 33 + d]     = co[ni][2];
            Os[(r0 + 8) * 33 + d + 1] = co[ni][3];
        }
    }
    __syncthreads();

    if (tid < 128) {
        int row = tid;
        int grow = qb * 128 + row;
        int token = b * N_PER_B + grow;
        float* Os = (float*)(smem + ATT_OS);
        float l = ((float*)(smem + ATT_LS))[row];
        float ov[DHEAD];
        #pragma unroll
        for (int d = 0; d < DHEAD; d++) ov[d] = Os[row * 33 + d];
        if (grow >= NCTX) {    // target self-attention term
            const bf16* kh = qh + (size_t)token * 768 + 256 + h * 32;
            const bf16* kl = ql + (size_t)token * 768 + 256 + h * 32;
            const bf16* vh = kh + 256;
            const bf16* vl = kl + 256;
            float s = 0.0f;
            #pragma unroll
            for (int d = 0; d < DHEAD; d++) {
                float qv = __bfloat162float(*(const bf16*)(smem + ATT_SQH + row * 80 + d * 2))
                         + __bfloat162float(*(const bf16*)(smem + ATT_SQL + row * 80 + d * 2));
                float kv = __bfloat162float(kh[d]) + __bfloat162float(kl[d]);
                s += qv * kv;
            }
            float p = __expf(fminf(s * SC, 70.0f));
            l += p;
            #pragma unroll
            for (int d = 0; d < DHEAD; d++)
                ov[d] += p * (__bfloat162float(vh[d]) + __bfloat162float(vl[d]));
        }
        float inv = 1.0f / l;
        size_t base = (size_t)token * DMODEL + h * DHEAD;
        #pragma unroll
        for (int d = 0; d < DHEAD; d += 2)
            store_bf16pair2(ohi + base + d, olo + base + d, ov[d] * inv, ov[d + 1] * inv);
    }
}

// ---------------- misc kernels ----------------
__global__ void build_zin_kernel(const float* __restrict__ xc,
                                 const float* __restrict__ yc,
                                 const float* __restrict__ xt,
                                 float* __restrict__ zin) {
    int t = blockIdx.x * blockDim.x + threadIdx.x;
    if (t >= T_TOTAL) return;
    int b = t >> 10;
    int i = t & 1023;
    float* o = zin + (size_t)t * 10;
    if (i < NCTX) {
        const float* xp = xc + ((size_t)b * NCTX + i) * 8;
        #pragma unroll
        for (int j = 0; j < 8; j++) o[j] = xp[j];
        o[8] = yc[(size_t)b * NCTX + i];
        o[9] = 0.0f;
    } else {
        const float* xp = xt + ((size_t)b * NCTX + (i - NCTX)) * 8;
        #pragma unroll
        for (int j = 0; j < 8; j++) o[j] = xp[j];
        o[8] = 0.0f;
        o[9] = 1.0f;
    }
}

__global__ __launch_bounds__(256) void enc1_kernel(
    const float* __restrict__ A, const float* __restrict__ B,
    const float* __restrict__ bias, bf16* __restrict__ Chi, bf16* __restrict__ Clo)
{
    const int BM = 128, BN = 64, BK = 16, N = DMODEL, K = 10;
    __shared__ float As[BK][BM + 1];
    __shared__ float Bs[BK][BN];
    int bm = blockIdx.y * BM;
    int bn = blockIdx.x * BN;
    int tid = threadIdx.x;
    int tx = tid & 15;
    int ty = tid >> 4;

    float acc[8][4];
    #pragma unroll
    for (int i = 0; i < 8; i++)
        #pragma unroll
        for (int j = 0; j < 4; j++) acc[i][j] = 0.0f;

    #pragma unroll
    for (int i = 0; i < 8; i++) {
        int idx = tid + i * 256;
        int m = idx >> 4, k = idx & 15;
        As[k][m] = (k < K) ? A[(size_t)(bm + m) * K + k] : 0.0f;
    }
    #pragma unroll
    for (int i = 0; i < 4; i++) {
        int idx = tid + i * 256;
        int k = idx >> 6, n = idx & 63;
        Bs[k][n] = (k < K) ? B[(size_t)k * N + bn + n] : 0.0f;
    }
    __syncthreads();
    #pragma unroll
    for (int k = 0; k < BK; k++) {
        float a[8];
        #pragma unroll
        for (int i = 0; i < 8; i++) a[i] = As[k][ty * 8 + i];
        float4 b4 = *(const float4*)&Bs[k][tx * 4];
        float b[4] = {b4.x, b4.y, b4.z, b4.w};
        #pragma unroll
        for (int i = 0; i < 8; i++)
            #pragma unroll
            for (int j = 0; j < 4; j++)
                acc[i][j] += a[i] * b[j];
    }

    #pragma unroll
    for (int i = 0; i < 8; i++) {
        int row = bm + ty * 8 + i;
        float4 v;
        v.x = fmaxf(acc[i][0] + bias[bn + tx * 4 + 0], 0.0f);
        v.y = fmaxf(acc[i][1] + bias[bn + tx * 4 + 1], 0.0f);
        v.z = fmaxf(acc[i][2] + bias[bn + tx * 4 + 2], 0.0f);
        v.w = fmaxf(acc[i][3] + bias[bn + tx * 4 + 3], 0.0f);
        size_t o = (size_t)row * N + bn + tx * 4;
        store_bf16pair4(Chi + o, Clo + o, v);
    }
}

__global__ __launch_bounds__(256) void ln_kernel(
    const float* __restrict__ z, const float* __restrict__ gamma,
    const float* __restrict__ beta, bf16* __restrict__ ohi, bf16* __restrict__ olo)
{
    int warp = threadIdx.x >> 5;
    int lane = threadIdx.x & 31;
    int t = blockIdx.x * 8 + warp;
    const float* zp = z + (size_t)t * DMODEL;

    float4 a = *(const float4*)(zp + lane * 4);
    float4 b = *(const float4*)(zp + 128 + lane * 4);
    float s  = a.x + a.y + a.z + a.w + b.x + b.y + b.z + b.w;
    float sq = a.x*a.x + a.y*a.y + a.z*a.z + a.w*a.w
             + b.x*b.x + b.y*b.y + b.z*b.z + b.w*b.w;
    #pragma unroll
    for (int o = 16; o > 0; o >>= 1) {
        s  += __shfl_xor_sync(0xffffffffu, s,  o);
        sq += __shfl_xor_sync(0xffffffffu, sq, o);
    }
    float mu = s * (1.0f / DMODEL);
    float var = sq * (1.0f / DMODEL) - mu * mu;
    float rs = rsqrtf(var + 1e-5f);

    float4 g0 = *(const float4*)(gamma + lane * 4);
    float4 g1 = *(const float4*)(gamma + 128 + lane * 4);
    float4 be0 = *(const float4*)(beta + lane * 4);
    float4 be1 = *(const float4*)(beta + 128 + lane * 4);
    float4 o0, o1;
    o0.x = (a.x - mu) * rs * g0.x + be0.x;
    o0.y = (a.y - mu) * rs * g0.y + be0.y;
    o0.z = (a.z - mu) * rs * g0.z + be0.z;
    o0.w = (a.w - mu) * rs * g0.w + be0.w;
    o1.x = (b.x - mu) * rs * g1.x + be1.x;
    o1.y = (b.y - mu) * rs * g1.y + be1.y;
    o1.z = (b.z - mu) * rs * g1.z + be1.z;
    o1.w = (b.w - mu) * rs * g1.w + be1.w;
    size_t base = (size_t)t * DMODEL;
    store_bf16pair4(ohi + base + lane * 4,       olo + base + lane * 4,       o0);
    store_bf16pair4(ohi + base + 128 + lane * 4, olo + base + 128 + lane * 4, o1);
}

// ---------------- launch ----------------
#define SMEM_BM128 81920
#define SMEM_BM64  61440

extern "C" void kernel_launch(void* const* d_in, const int* in_sizes, int n_in,
                              void* d_out, int out_size) {
    const float* xc     = (const float*)d_in[0];
    const float* yc     = (const float*)d_in[1];
    const float* xt     = (const float*)d_in[2];
    const float* enc_W1 = (const float*)d_in[3];
    const float* enc_b1 = (const float*)d_in[4];
    const float* enc_W2 = (const float*)d_in[5];
    const float* enc_b2 = (const float*)d_in[6];
    const float* Wqkv   = (const float*)d_in[7];
    const float* bqkv   = (const float*)d_in[8];
    const float* Wo     = (const float*)d_in[9];
    const float* bo     = (const float*)d_in[10];
    const float* ln1_g  = (const float*)d_in[11];
    const float* ln1_b  = (const float*)d_in[12];
    const float* ln2_g  = (const float*)d_in[13];
    const float* ln2_b  = (const float*)d_in[14];
    const float* Wff1   = (const float*)d_in[15];
    const float* bff1   = (const float*)d_in[16];
    const float* Wff2   = (const float*)d_in[17];
    const float* bff2   = (const float*)d_in[18];

    float *zin, *zb;
    bf16 *ahi, *alo, *fhi, *flo, *wThi, *wTlo, *qkh, *qkl, *vth, *vtl;
    cudaGetSymbolAddress((void**)&zin,  g_zin);
    cudaGetSymbolAddress((void**)&zb,   g_z);
    cudaGetSymbolAddress((void**)&ahi,  g_ahi);
    cudaGetSymbolAddress((void**)&alo,  g_alo);
    cudaGetSymbolAddress((void**)&fhi,  g_fhi);
    cudaGetSymbolAddress((void**)&flo,  g_flo);
    cudaGetSymbolAddress((void**)&wThi, g_wThi);
    cudaGetSymbolAddress((void**)&wTlo, g_wTlo);
    cudaGetSymbolAddress((void**)&qkh,  g_qkvh);
    cudaGetSymbolAddress((void**)&qkl,  g_qkvl);
    cudaGetSymbolAddress((void**)&vth,  g_vTh);
    cudaGetSymbolAddress((void**)&vtl,  g_vTl);

    cudaFuncSetAttribute(gemm_mma<128, 0, 0, 1, 0>, cudaFuncAttributeMaxDynamicSharedMemorySize, SMEM_BM128);
    cudaFuncSetAttribute(gemm_mma<128, 1, 0, 1, 0>, cudaFuncAttributeMaxDynamicSharedMemorySize, SMEM_BM128);
    cudaFuncSetAttribute(gemm_mma<64, 0, 0, 0, 0>,  cudaFuncAttributeMaxDynamicSharedMemorySize, SMEM_BM64);
    cudaFuncSetAttribute(gemm_mma<64, 0, 1, 0, 0>,  cudaFuncAttributeMaxDynamicSharedMemorySize, SMEM_BM64);
    cudaFuncSetAttribute(gemm_mma<64, 0, 1, 0, 1>,  cudaFuncAttributeMaxDynamicSharedMemorySize, SMEM_BM64);
    cudaFuncSetAttribute(attn_mma, cudaFuncAttributeMaxDynamicSharedMemorySize, ATT_SMEM);

    tr_all<<<dim3(32, 32, 25), dim3(32, 8)>>>(enc_W2, Wqkv, Wo, Wff1, Wff2, wThi, wTlo);

    build_zin_kernel<<<32, 256>>>(xc, yc, xt, zin);
    enc1_kernel<<<dim3(DMODEL / 64, T_TOTAL / 128), 256>>>(zin, enc_W1, enc_b1, ahi, alo);
    gemm_mma<64, 0, 0, 0, 0><<<dim3(2, 128), 256, SMEM_BM64>>>(
        ahi, alo, wThi, wTlo, enc_b2, zb, nullptr, nullptr, nullptr, 256, 256);

    for (int l = 0; l < LAYERS; l++) {
        size_t base = 65536 + (size_t)l * 786432;
        ln_kernel<<<T_TOTAL / 8, 256>>>(zb, ln1_g + l * DMODEL, ln1_b + l * DMODEL, ahi, alo);
        gemm_mma<128, 0, 0, 1, 0><<<dim3(6, 64), 256, SMEM_BM128>>>(
            ahi, alo, wThi + base, wTlo + base, bqkv + l * 768,
            nullptr, qkh, qkl, nullptr, 768, 256);
        vt_kernel<<<dim3(32, 8, 8), dim3(32, 8)>>>(qkh, qkl, vth, vtl);
        attn_mma<<<dim3(8, 8, 8), 256, ATT_SMEM>>>(qkh, qkl, vth, vtl, ahi, alo);
        gemm_mma<64, 0, 1, 0, 0><<<dim3(2, 128), 256, SMEM_BM64>>>(
            ahi, alo, wThi + base + 196608, wTlo + base + 196608, bo + l * DMODEL,
            zb, nullptr, nullptr, nullptr, 256, 256);
        ln_kernel<<<T_TOTAL / 8, 256>>>(zb, ln2_g + l * DMODEL, ln2_b + l * DMODEL, ahi, alo);
        gemm_mma<128, 1, 0, 1, 0><<<dim3(8, 64), 256, SMEM_BM128>>>(
            ahi, alo, wThi + base + 262144, wTlo + base + 262144, bff1 + l * FFDIM,
            nullptr, fhi, flo, nullptr, 1024, 256);
        if (l < LAYERS - 1) {
            gemm_mma<64, 0, 1, 0, 0><<<dim3(2, 128), 256, SMEM_BM64>>>(
                fhi, flo, wThi + base + 524288, wTlo + base + 524288, bff2 + l * DMODEL,
                zb, nullptr, nullptr, nullptr, 256, 1024);
        } else {
            gemm_mma<64, 0, 1, 0, 1><<<dim3(2, 128), 256, SMEM_BM64>>>(
                fhi, flo, wThi + base + 524288, wTlo + base + 524288, bff2 + l * DMODEL,
                zb, nullptr, nullptr, (float*)d_out, 256, 1024);
        }
    }
}

// round 13
// speedup vs baseline: 1.4209x; 1.0155x over previous
#include <cuda_runtime.h>
#include <cuda_bf16.h>
#include <math.h>
#include <stdint.h>

#define T_TOTAL 8192
#define N_PER_B 1024
#define NCTX    512
#define DMODEL  256
#define HEADS   8
#define DHEAD   32
#define LAYERS  6
#define FFDIM   1024

typedef __nv_bfloat16 bf16;

__device__ float g_zin[T_TOTAL * 10];
__device__ float g_z  [T_TOTAL * DMODEL];
__device__ bf16  g_ahi[T_TOTAL * DMODEL];
__device__ bf16  g_alo[T_TOTAL * DMODEL];
__device__ bf16  g_fhi[T_TOTAL * FFDIM];
__device__ bf16  g_flo[T_TOTAL * FFDIM];
__device__ bf16  g_qkvh[T_TOTAL * 768];
__device__ bf16  g_qkvl[T_TOTAL * 768];
#define WT_TOTAL 4784128
__device__ bf16  g_wThi[WT_TOTAL];
__device__ bf16  g_wTlo[WT_TOTAL];

// ---------------- PTX helpers ----------------
__device__ __forceinline__ uint32_t smem_u32(const void* p) {
    uint32_t a;
    asm("{ .reg .u64 t; cvta.to.shared.u64 t, %1; cvt.u32.u64 %0, t; }"
        : "=r"(a) : "l"(p));
    return a;
}
__device__ __forceinline__ void cp16(uint32_t saddr, const void* g) {
    asm volatile("cp.async.cg.shared.global [%0], [%1], 16;"
                 :: "r"(saddr), "l"(g) : "memory");
}
__device__ __forceinline__ void cp_commit() {
    asm volatile("cp.async.commit_group;" ::: "memory");
}
__device__ __forceinline__ void cp_wait2() {
    asm volatile("cp.async.wait_group 2;" ::: "memory");
}
__device__ __forceinline__ void cp_wait1() {
    asm volatile("cp.async.wait_group 1;" ::: "memory");
}
__device__ __forceinline__ void cp_wait0() {
    asm volatile("cp.async.wait_group 0;" ::: "memory");
}
__device__ __forceinline__ void ldm4(uint32_t* d, uint32_t addr) {
    asm volatile("ldmatrix.sync.aligned.m8n8.x4.shared.b16 {%0,%1,%2,%3}, [%4];"
        : "=r"(d[0]), "=r"(d[1]), "=r"(d[2]), "=r"(d[3]) : "r"(addr));
}
__device__ __forceinline__ void ldm4t(uint32_t* d, uint32_t addr) {
    asm volatile("ldmatrix.sync.aligned.m8n8.x4.trans.shared.b16 {%0,%1,%2,%3}, [%4];"
        : "=r"(d[0]), "=r"(d[1]), "=r"(d[2]), "=r"(d[3]) : "r"(addr));
}
__device__ __forceinline__ void mma16816(float* c, const uint32_t* a,
                                         uint32_t b0, uint32_t b1) {
    asm volatile(
        "mma.sync.aligned.m16n8k16.row.col.f32.bf16.bf16.f32 "
        "{%0,%1,%2,%3}, {%4,%5,%6,%7}, {%8,%9}, {%0,%1,%2,%3};"
        : "+f"(c[0]), "+f"(c[1]), "+f"(c[2]), "+f"(c[3])
        : "r"(a[0]), "r"(a[1]), "r"(a[2]), "r"(a[3]), "r"(b0), "r"(b1));
}

// ---------------- bf16 split helpers ----------------
__device__ __forceinline__ unsigned pk(bf16 a, bf16 b) {
    unsigned short ua = *(unsigned short*)&a;
    unsigned short ub = *(unsigned short*)&b;
    return (unsigned)ua | ((unsigned)ub << 16);
}
__device__ __forceinline__ void store_bf16pair4(bf16* ph, bf16* pl, float4 v) {
    bf16 h0 = __float2bfloat16(v.x), h1 = __float2bfloat16(v.y);
    bf16 h2 = __float2bfloat16(v.z), h3 = __float2bfloat16(v.w);
    uint2 uh; uh.x = pk(h0, h1); uh.y = pk(h2, h3);
    uint2 ul;
    ul.x = pk(__float2bfloat16(v.x - __bfloat162float(h0)),
              __float2bfloat16(v.y - __bfloat162float(h1)));
    ul.y = pk(__float2bfloat16(v.z - __bfloat162float(h2)),
              __float2bfloat16(v.w - __bfloat162float(h3)));
    *(uint2*)ph = uh;
    *(uint2*)pl = ul;
}
__device__ __forceinline__ void store_bf16pair2(bf16* ph, bf16* pl, float a, float b) {
    bf16 h0 = __float2bfloat16(a), h1 = __float2bfloat16(b);
    *(unsigned*)ph = pk(h0, h1);
    *(unsigned*)pl = pk(__float2bfloat16(a - __bfloat162float(h0)),
                        __float2bfloat16(b - __bfloat162float(h1)));
}

// ---------------- all weight transposes, ONE launch ----------------
__global__ void tr_all(const float* __restrict__ encW2,
                       const float* __restrict__ Wqkv, const float* __restrict__ Wo,
                       const float* __restrict__ Wff1, const float* __restrict__ Wff2,
                       bf16* __restrict__ oh, bf16* __restrict__ ol) {
    __shared__ float t[32][33];
    int z = blockIdx.z;
    const float* W; int K, N; size_t off;
    if (z == 0) { W = encW2; K = 256; N = 256; off = 0; }
    else {
        int l = (z - 1) >> 2, k = (z - 1) & 3;
        size_t base = 65536 + (size_t)l * 786432;
        if (k == 0)      { W = Wqkv + (size_t)l * 196608; K = 256;  N = 768;  off = base; }
        else if (k == 1) { W = Wo   + (size_t)l * 65536;  K = 256;  N = 256;  off = base + 196608; }
        else if (k == 2) { W = Wff1 + (size_t)l * 262144; K = 256;  N = 1024; off = base + 262144; }
        else             { W = Wff2 + (size_t)l * 262144; K = 1024; N = 256;  off = base + 524288; }
    }
    int n0 = blockIdx.x * 32, k0 = blockIdx.y * 32;
    if (n0 >= N || k0 >= K) return;
    int tx = threadIdx.x, ty = threadIdx.y;
    #pragma unroll
    for (int i = 0; i < 4; i++)
        t[ty + i * 8][tx] = W[(size_t)(k0 + ty + i * 8) * N + n0 + tx];
    __syncthreads();
    #pragma unroll
    for (int i = 0; i < 4; i++) {
        float v = t[tx][ty + i * 8];
        bf16 h = __float2bfloat16(v);
        size_t o = off + (size_t)(n0 + ty + i * 8) * K + k0 + tx;
        oh[o] = h;
        ol[o] = __float2bfloat16(v - __bfloat162float(h));
    }
}

// ---------------- warp-MMA GEMM (3-pass bf16 hi/lo) ----------------
// BM64: 3-stage cp.async pipeline; BM128: 2-stage. 2 CTAs/SM both.
template<int BM, int RELU, int RES, int OUTBF, int FIN>
__global__ __launch_bounds__(256, 2) void gemm_mma(
    const bf16* __restrict__ Ahi, const bf16* __restrict__ Alo,
    const bf16* __restrict__ Bhi, const bf16* __restrict__ Blo,
    const float* __restrict__ bias,
    float* __restrict__ Cf, bf16* __restrict__ Chi, bf16* __restrict__ Clo,
    float* __restrict__ Cout, int N, int K)
{
    constexpr int MI = BM / 32;
    constexpr int NS = (BM == 64) ? 3 : 2;
    constexpr int STAGE = (2 * BM + 256) * 80;
    constexpr int OAh = 0;
    constexpr int OAl = BM * 80;
    constexpr int OBh = 2 * BM * 80;
    constexpr int OBl = 2 * BM * 80 + 128 * 80;

    extern __shared__ char smem[];
    const int tid = threadIdx.x;
    const int wid = tid >> 5, lane = tid & 31;
    const int wm = wid & 1, wn = wid >> 1;
    const int bn = blockIdx.x * 128, bm = blockIdx.y * BM;
    const uint32_t sb = smem_u32(smem);

    float c[MI][4][4];
    #pragma unroll
    for (int i = 0; i < MI; i++)
        #pragma unroll
        for (int j = 0; j < 4; j++)
            #pragma unroll
            for (int q = 0; q < 4; q++) c[i][j][q] = 0.0f;

    const int r8 = lane & 7, g8 = lane >> 3;
    const int a_row = wm * (BM / 2) + (g8 & 1) * 8 + r8;
    const int a_kof = (g8 >> 1) * 16;
    const int b_row = wn * 32 + (g8 >> 1) * 8 + r8;
    const int b_kof = (g8 & 1) * 16;

    auto load_stage = [&](int s, int buf) {
        const int k0 = s * 32;
        const uint32_t sbase = sb + buf * STAGE;
        #pragma unroll
        for (int i = tid; i < BM * 4; i += 256) {
            int r = i >> 2, cc = i & 3;
            size_t g = (size_t)(bm + r) * K + k0 + cc * 8;
            uint32_t so = sbase + r * 80 + cc * 16;
            cp16(so + OAh, Ahi + g);
            cp16(so + OAl, Alo + g);
        }
        #pragma unroll
        for (int i = tid; i < 512; i += 256) {
            int r = i >> 2, cc = i & 3;
            size_t g = (size_t)(bn + r) * K + k0 + cc * 8;
            uint32_t so = sbase + r * 80 + cc * 16;
            cp16(so + OBh, Bhi + g);
            cp16(so + OBl, Blo + g);
        }
        cp_commit();
    };

    const int S = K >> 5;
    int issued = 0;
    load_stage(0, 0); issued++;
    if (NS >= 3 && issued < S) { load_stage(1, 1); issued++; }

    for (int s = 0; s < S; s++) {
        if (issued < S) { load_stage(issued, issued % NS); issued++; }
        int allow = issued - s - 1;
        if (allow >= 2) cp_wait2();
        else if (allow == 1) cp_wait1();
        else cp_wait0();
        __syncthreads();

        const uint32_t sbase = sb + (s % NS) * STAGE;
        #pragma unroll
        for (int ks = 0; ks < 2; ks++) {
            uint32_t a[MI][4], bh[2][4], bl[2][4];
            #pragma unroll
            for (int mi = 0; mi < MI; mi++)
                ldm4(a[mi], sbase + OAh + (uint32_t)(a_row + mi * 16) * 80 + ks * 32 + a_kof);
            #pragma unroll
            for (int nj = 0; nj < 2; nj++)
                ldm4(bh[nj], sbase + OBh + (uint32_t)(b_row + nj * 16) * 80 + ks * 32 + b_kof);
            #pragma unroll
            for (int mi = 0; mi < MI; mi++)
                #pragma unroll
                for (int ni = 0; ni < 4; ni++)
                    mma16816(c[mi][ni], a[mi], bh[ni >> 1][(ni & 1) * 2], bh[ni >> 1][(ni & 1) * 2 + 1]);
            #pragma unroll
            for (int nj = 0; nj < 2; nj++)
                ldm4(bl[nj], sbase + OBl + (uint32_t)(b_row + nj * 16) * 80 + ks * 32 + b_kof);
            #pragma unroll
            for (int mi = 0; mi < MI; mi++)
                #pragma unroll
                for (int ni = 0; ni < 4; ni++)
                    mma16816(c[mi][ni], a[mi], bl[ni >> 1][(ni & 1) * 2], bl[ni >> 1][(ni & 1) * 2 + 1]);
            #pragma unroll
            for (int mi = 0; mi < MI; mi++)
                ldm4(a[mi], sbase + OAl + (uint32_t)(a_row + mi * 16) * 80 + ks * 32 + a_kof);
            #pragma unroll
            for (int mi = 0; mi < MI; mi++)
                #pragma unroll
                for (int ni = 0; ni < 4; ni++)
                    mma16816(c[mi][ni], a[mi], bh[ni >> 1][(ni & 1) * 2], bh[ni >> 1][(ni & 1) * 2 + 1]);
        }
        __syncthreads();
    }

    const int quad = lane >> 2, tc = lane & 3;
    #pragma unroll
    for (int mi = 0; mi < MI; mi++) {
        #pragma unroll
        for (int ni = 0; ni < 4; ni++) {
            int row0 = bm + wm * (BM / 2) + mi * 16 + quad;
            int col = bn + wn * 32 + ni * 8 + tc * 2;
            float b0 = bias[col], b1 = bias[col + 1];
            float v00 = c[mi][ni][0] + b0, v01 = c[mi][ni][1] + b1;
            float v10 = c[mi][ni][2] + b0, v11 = c[mi][ni][3] + b1;
            if (RELU) {
                v00 = fmaxf(v00, 0.0f); v01 = fmaxf(v01, 0.0f);
                v10 = fmaxf(v10, 0.0f); v11 = fmaxf(v11, 0.0f);
            }
            size_t o0 = (size_t)row0 * N + col;
            size_t o1 = o0 + (size_t)8 * N;
            if (OUTBF) {
                store_bf16pair2(Chi + o0, Clo + o0, v00, v01);
                store_bf16pair2(Chi + o1, Clo + o1, v10, v11);
            } else if (RES) {
                float2 z0 = *(float2*)(Cf + o0);
                float2 z1 = *(float2*)(Cf + o1);
                z0.x += v00; z0.y += v01; z1.x += v10; z1.y += v11;
                *(float2*)(Cf + o0) = z0;
                *(float2*)(Cf + o1) = z1;
                if (FIN) {
                    *(float2*)(Cout + o0) = z0;
                    *(float2*)(Cout + o1) = z1;
                }
            } else {
                float2 w0 = {v00, v01}, w1 = {v10, v11};
                *(float2*)(Cf + o0) = w0;
                *(float2*)(Cf + o1) = w1;
            }
        }
    }
}

// ---------------- MMA flash attention, fixed-max softmax ----------------
// V consumed directly from qkv (K-major rows) via ldmatrix.trans — no vT pass.
#define ATT_SQH  0
#define ATT_SQL  10240
#define ATT_BUF0 20480
#define ATT_KH   0
#define ATT_KL   10240
#define ATT_VH   20480
#define ATT_VL   30720
#define ATT_BUFSZ 40960
#define ATT_OS   20480            /* aliases buf0: only used after mainloop */
#define ATT_LS   (20480 + 16896)
#define ATT_SMEM 102400

__global__ __launch_bounds__(256) void attn_mma(
    const bf16* __restrict__ qh, const bf16* __restrict__ ql,
    bf16* __restrict__ ohi, bf16* __restrict__ olo)
{
    extern __shared__ char smem[];
    const int tid = threadIdx.x, wid = tid >> 5, lane = tid & 31;
    const int qb = blockIdx.x, h = blockIdx.y, b = blockIdx.z;
    const uint32_t sb = smem_u32(smem);
    const float SC = 0.17677669529663689f;

    const int r8 = lane & 7, g8 = lane >> 3;

    // Q tile [128 x 32] hi/lo
    #pragma unroll
    for (int i = 0; i < 4; i++) {
        int idx = tid + i * 256;
        int st = idx >> 9, rem = idx & 511;
        int r = rem >> 2, cc = rem & 3;
        int token = b * N_PER_B + qb * 128 + r;
        const bf16* src = (st ? ql : qh) + (size_t)token * 768 + h * 32 + cc * 8;
        cp16(sb + (st ? ATT_SQL : ATT_SQH) + r * 80 + cc * 16, src);
    }
    auto load_kv = [&](int c, int buf) {
        uint32_t base = sb + ATT_BUF0 + buf * ATT_BUFSZ;
        #pragma unroll
        for (int i = 0; i < 4; i++) {
            int idx = tid + i * 256;
            int st = idx >> 9, rem = idx & 511;
            int r = rem >> 2, cc = rem & 3;
            int token = b * N_PER_B + c * 128 + r;
            const bf16* src = (st ? ql : qh) + (size_t)token * 768 + 256 + h * 32 + cc * 8;
            cp16(base + (st ? ATT_KL : ATT_KH) + r * 80 + cc * 16, src);
        }
        #pragma unroll
        for (int i = 0; i < 4; i++) {
            int idx = tid + i * 256;
            int st = idx >> 9, rem = idx & 511;
            int r = rem >> 2, cc = rem & 3;
            int token = b * N_PER_B + c * 128 + r;
            const bf16* src = (st ? ql : qh) + (size_t)token * 768 + 512 + h * 32 + cc * 8;
            cp16(base + (st ? ATT_VL : ATT_VH) + r * 80 + cc * 16, src);
        }
        cp_commit();
    };
    load_kv(0, 0);   // group0 = Q + KV0

    float co[4][4];
    #pragma unroll
    for (int i = 0; i < 4; i++)
        #pragma unroll
        for (int j = 0; j < 4; j++) co[i][j] = 0.0f;
    float l0 = 0.0f, l1 = 0.0f;
    uint32_t qfh[2][4], qfl[2][4];

    const int a_row = wid * 16 + (g8 & 1) * 8 + r8;
    const int a_kof = (g8 >> 1) * 16;
    const int b_r8 = (g8 >> 1) * 8 + r8;
    const int b_kof = (g8 & 1) * 16;
    // trans addressing for V (K-major rows): row = k-chunk, byteoff = d
    const int v_r8 = (g8 & 1) * 8 + r8;
    const int v_dof = (g8 >> 1) * 16;

    for (int c = 0; c < 4; c++) {
        if (c < 3) { load_kv(c + 1, (c + 1) & 1); cp_wait1(); }
        else cp_wait0();
        __syncthreads();
        if (c == 0) {
            #pragma unroll
            for (int ks = 0; ks < 2; ks++) {
                ldm4(qfh[ks], sb + ATT_SQH + (uint32_t)a_row * 80 + ks * 32 + a_kof);
                ldm4(qfl[ks], sb + ATT_SQL + (uint32_t)a_row * 80 + ks * 32 + a_kof);
            }
        }
        const uint32_t kb = sb + ATT_BUF0 + (c & 1) * ATT_BUFSZ;

        // S[16 x 128] = Q Kt (3-pass)
        float cs[16][4];
        #pragma unroll
        for (int t = 0; t < 16; t++)
            #pragma unroll
            for (int q = 0; q < 4; q++) cs[t][q] = 0.0f;
        #pragma unroll
        for (int ks = 0; ks < 2; ks++) {
            #pragma unroll
            for (int nj = 0; nj < 8; nj++) {
                uint32_t kf[4];
                uint32_t ra = kb + ATT_KH + (uint32_t)(nj * 16 + b_r8) * 80 + ks * 32 + b_kof;
                ldm4(kf, ra);
                mma16816(cs[2 * nj],     qfh[ks], kf[0], kf[1]);
                mma16816(cs[2 * nj + 1], qfh[ks], kf[2], kf[3]);
                mma16816(cs[2 * nj],     qfl[ks], kf[0], kf[1]);
                mma16816(cs[2 * nj + 1], qfl[ks], kf[2], kf[3]);
                ldm4(kf, ra + (ATT_KL - ATT_KH));
                mma16816(cs[2 * nj],     qfh[ks], kf[0], kf[1]);
                mma16816(cs[2 * nj + 1], qfh[ks], kf[2], kf[3]);
            }
        }

        // P = exp(S*scale) (fixed max), split hi/lo
        uint32_t pph0[16], pph1[16], ppl0[16], ppl1[16];
        #pragma unroll
        for (int t = 0; t < 16; t++) {
            float p0 = __expf(fminf(cs[t][0] * SC, 70.0f));
            float p1 = __expf(fminf(cs[t][1] * SC, 70.0f));
            float p2 = __expf(fminf(cs[t][2] * SC, 70.0f));
            float p3 = __expf(fminf(cs[t][3] * SC, 70.0f));
            l0 += p0 + p1; l1 += p2 + p3;
            bf16 h0 = __float2bfloat16(p0), h1 = __float2bfloat16(p1);
            bf16 h2 = __float2bfloat16(p2), h3 = __float2bfloat16(p3);
            pph0[t] = pk(h0, h1);
            pph1[t] = pk(h2, h3);
            ppl0[t] = pk(__float2bfloat16(p0 - __bfloat162float(h0)),
                         __float2bfloat16(p1 - __bfloat162float(h1)));
            ppl1[t] = pk(__float2bfloat16(p2 - __bfloat162float(h2)),
                         __float2bfloat16(p3 - __bfloat162float(h3)));
        }

        // O += P * V (3-pass), V via ldmatrix.trans from K-major rows
        #pragma unroll
        for (int j = 0; j < 8; j++) {
            uint32_t Ah[4] = {pph0[2 * j], pph1[2 * j], pph0[2 * j + 1], pph1[2 * j + 1]};
            uint32_t Al[4] = {ppl0[2 * j], ppl1[2 * j], ppl0[2 * j + 1], ppl1[2 * j + 1]};
            #pragma unroll
            for (int nv = 0; nv < 2; nv++) {
                uint32_t vf[4];
                uint32_t ra = kb + ATT_VH + (uint32_t)(j * 16 + v_r8) * 80 + nv * 32 + v_dof;
                ldm4t(vf, ra);
                mma16816(co[2 * nv],     Ah, vf[0], vf[1]);
                mma16816(co[2 * nv + 1], Ah, vf[2], vf[3]);
                mma16816(co[2 * nv],     Al, vf[0], vf[1]);
                mma16816(co[2 * nv + 1], Al, vf[2], vf[3]);
                ldm4t(vf, ra + (ATT_VL - ATT_VH));
                mma16816(co[2 * nv],     Ah, vf[0], vf[1]);
                mma16816(co[2 * nv + 1], Ah, vf[2], vf[3]);
            }
        }
        __syncthreads();
    }

    l0 += __shfl_xor_sync(0xffffffffu, l0, 1);
    l0 += __shfl_xor_sync(0xffffffffu, l0, 2);
    l1 += __shfl_xor_sync(0xffffffffu, l1, 1);
    l1 += __shfl_xor_sync(0xffffffffu, l1, 2);
    {
        const int g = lane >> 2, tc = lane & 3;
        float* Os = (float*)(smem + ATT_OS);
        float* Ls = (float*)(smem + ATT_LS);
        int r0 = wid * 16 + g;
        if (tc == 0) { Ls[r0] = l0; Ls[r0 + 8] = l1; }
        #pragma unroll
        for (int ni = 0; ni < 4; ni++) {
            int d = ni * 8 + tc * 2;
            Os[r0 * 33 + d]           = co[ni][0];
            Os[r0 * 33 + d + 1]       = co[ni][1];
            Os[(r0 + 8) * 33 + d]     = co[ni][2];
            Os[(r0 + 8) * 33 + d + 1] = co[ni][3];
        }
    }
    __syncthreads();

    if (tid < 128) {
        int row = tid;
        int grow = qb * 128 + row;
        int token = b * N_PER_B + grow;
        float* Os = (float*)(smem + ATT_OS);
        float l = ((float*)(smem + ATT_LS))[row];
        float ov[DHEAD];
        #pragma unroll
        for (int d = 0; d < DHEAD; d++) ov[d] = Os[row * 33 + d];
        if (grow >= NCTX) {    // target self-attention term
            const bf16* kh = qh + (size_t)token * 768 + 256 + h * 32;
            const bf16* kl = ql + (size_t)token * 768 + 256 + h * 32;
            const bf16* vh = kh + 256;
            const bf16* vl = kl + 256;
            float s = 0.0f;
            #pragma unroll
            for (int d = 0; d < DHEAD; d++) {
                float qv = __bfloat162float(*(const bf16*)(smem + ATT_SQH + row * 80 + d * 2))
                         + __bfloat162float(*(const bf16*)(smem + ATT_SQL + row * 80 + d * 2));
                float kv = __bfloat162float(kh[d]) + __bfloat162float(kl[d]);
                s += qv * kv;
            }
            float p = __expf(fminf(s * SC, 70.0f));
            l += p;
            #pragma unroll
            for (int d = 0; d < DHEAD; d++)
                ov[d] += p * (__bfloat162float(vh[d]) + __bfloat162float(vl[d]));
        }
        float inv = 1.0f / l;
        size_t base = (size_t)token * DMODEL + h * DHEAD;
        #pragma unroll
        for (int d = 0; d < DHEAD; d += 2)
            store_bf16pair2(ohi + base + d, olo + base + d, ov[d] * inv, ov[d + 1] * inv);
    }
}

// ---------------- misc kernels ----------------
__global__ void build_zin_kernel(const float* __restrict__ xc,
                                 const float* __restrict__ yc,
                                 const float* __restrict__ xt,
                                 float* __restrict__ zin) {
    int t = blockIdx.x * blockDim.x + threadIdx.x;
    if (t >= T_TOTAL) return;
    int b = t >> 10;
    int i = t & 1023;
    float* o = zin + (size_t)t * 10;
    if (i < NCTX) {
        const float* xp = xc + ((size_t)b * NCTX + i) * 8;
        #pragma unroll
        for (int j = 0; j < 8; j++) o[j] = xp[j];
        o[8] = yc[(size_t)b * NCTX + i];
        o[9] = 0.0f;
    } else {
        const float* xp = xt + ((size_t)b * NCTX + (i - NCTX)) * 8;
        #pragma unroll
        for (int j = 0; j < 8; j++) o[j] = xp[j];
        o[8] = 0.0f;
        o[9] = 1.0f;
    }
}

__global__ __launch_bounds__(256) void enc1_kernel(
    const float* __restrict__ A, const float* __restrict__ B,
    const float* __restrict__ bias, bf16* __restrict__ Chi, bf16* __restrict__ Clo)
{
    const int BM = 128, BN = 64, BK = 16, N = DMODEL, K = 10;
    __shared__ float As[BK][BM + 1];
    __shared__ float Bs[BK][BN];
    int bm = blockIdx.y * BM;
    int bn = blockIdx.x * BN;
    int tid = threadIdx.x;
    int tx = tid & 15;
    int ty = tid >> 4;

    float acc[8][4];
    #pragma unroll
    for (int i = 0; i < 8; i++)
        #pragma unroll
        for (int j = 0; j < 4; j++) acc[i][j] = 0.0f;

    #pragma unroll
    for (int i = 0; i < 8; i++) {
        int idx = tid + i * 256;
        int m = idx >> 4, k = idx & 15;
        As[k][m] = (k < K) ? A[(size_t)(bm + m) * K + k] : 0.0f;
    }
    #pragma unroll
    for (int i = 0; i < 4; i++) {
        int idx = tid + i * 256;
        int k = idx >> 6, n = idx & 63;
        Bs[k][n] = (k < K) ? B[(size_t)k * N + bn + n] : 0.0f;
    }
    __syncthreads();
    #pragma unroll
    for (int k = 0; k < BK; k++) {
        float a[8];
        #pragma unroll
        for (int i = 0; i < 8; i++) a[i] = As[k][ty * 8 + i];
        float4 b4 = *(const float4*)&Bs[k][tx * 4];
        float b[4] = {b4.x, b4.y, b4.z, b4.w};
        #pragma unroll
        for (int i = 0; i < 8; i++)
            #pragma unroll
            for (int j = 0; j < 4; j++)
                acc[i][j] += a[i] * b[j];
    }

    #pragma unroll
    for (int i = 0; i < 8; i++) {
        int row = bm + ty * 8 + i;
        float4 v;
        v.x = fmaxf(acc[i][0] + bias[bn + tx * 4 + 0], 0.0f);
        v.y = fmaxf(acc[i][1] + bias[bn + tx * 4 + 1], 0.0f);
        v.z = fmaxf(acc[i][2] + bias[bn + tx * 4 + 2], 0.0f);
        v.w = fmaxf(acc[i][3] + bias[bn + tx * 4 + 3], 0.0f);
        size_t o = (size_t)row * N + bn + tx * 4;
        store_bf16pair4(Chi + o, Clo + o, v);
    }
}

__global__ __launch_bounds__(256) void ln_kernel(
    const float* __restrict__ z, const float* __restrict__ gamma,
    const float* __restrict__ beta, bf16* __restrict__ ohi, bf16* __restrict__ olo)
{
    int warp = threadIdx.x >> 5;
    int lane = threadIdx.x & 31;
    int t = blockIdx.x * 8 + warp;
    const float* zp = z + (size_t)t * DMODEL;

    float4 a = *(const float4*)(zp + lane * 4);
    float4 b = *(const float4*)(zp + 128 + lane * 4);
    float s  = a.x + a.y + a.z + a.w + b.x + b.y + b.z + b.w;
    float sq = a.x*a.x + a.y*a.y + a.z*a.z + a.w*a.w
             + b.x*b.x + b.y*b.y + b.z*b.z + b.w*b.w;
    #pragma unroll
    for (int o = 16; o > 0; o >>= 1) {
        s  += __shfl_xor_sync(0xffffffffu, s,  o);
        sq += __shfl_xor_sync(0xffffffffu, sq, o);
    }
    float mu = s * (1.0f / DMODEL);
    float var = sq * (1.0f / DMODEL) - mu * mu;
    float rs = rsqrtf(var + 1e-5f);

    float4 g0 = *(const float4*)(gamma + lane * 4);
    float4 g1 = *(const float4*)(gamma + 128 + lane * 4);
    float4 be0 = *(const float4*)(beta + lane * 4);
    float4 be1 = *(const float4*)(beta + 128 + lane * 4);
    float4 o0, o1;
    o0.x = (a.x - mu) * rs * g0.x + be0.x;
    o0.y = (a.y - mu) * rs * g0.y + be0.y;
    o0.z = (a.z - mu) * rs * g0.z + be0.z;
    o0.w = (a.w - mu) * rs * g0.w + be0.w;
    o1.x = (b.x - mu) * rs * g1.x + be1.x;
    o1.y = (b.y - mu) * rs * g1.y + be1.y;
    o1.z = (b.z - mu) * rs * g1.z + be1.z;
    o1.w = (b.w - mu) * rs * g1.w + be1.w;
    size_t base = (size_t)t * DMODEL;
    store_bf16pair4(ohi + base + lane * 4,       olo + base + lane * 4,       o0);
    store_bf16pair4(ohi + base + 128 + lane * 4, olo + base + 128 + lane * 4, o1);
}

// ---------------- launch ----------------
#define SMEM_BM128 81920   // 2 stages
#define SMEM_BM64  92160   // 3 stages

extern "C" void kernel_launch(void* const* d_in, const int* in_sizes, int n_in,
                              void* d_out, int out_size) {
    const float* xc     = (const float*)d_in[0];
    const float* yc     = (const float*)d_in[1];
    const float* xt     = (const float*)d_in[2];
    const float* enc_W1 = (const float*)d_in[3];
    const float* enc_b1 = (const float*)d_in[4];
    const float* enc_W2 = (const float*)d_in[5];
    const float* enc_b2 = (const float*)d_in[6];
    const float* Wqkv   = (const float*)d_in[7];
    const float* bqkv   = (const float*)d_in[8];
    const float* Wo     = (const float*)d_in[9];
    const float* bo     = (const float*)d_in[10];
    const float* ln1_g  = (const float*)d_in[11];
    const float* ln1_b  = (const float*)d_in[12];
    const float* ln2_g  = (const float*)d_in[13];
    const float* ln2_b  = (const float*)d_in[14];
    const float* Wff1   = (const float*)d_in[15];
    const float* bff1   = (const float*)d_in[16];
    const float* Wff2   = (const float*)d_in[17];
    const float* bff2   = (const float*)d_in[18];

    float *zin, *zb;
    bf16 *ahi, *alo, *fhi, *flo, *wThi, *wTlo, *qkh, *qkl;
    cudaGetSymbolAddress((void**)&zin,  g_zin);
    cudaGetSymbolAddress((void**)&zb,   g_z);
    cudaGetSymbolAddress((void**)&ahi,  g_ahi);
    cudaGetSymbolAddress((void**)&alo,  g_alo);
    cudaGetSymbolAddress((void**)&fhi,  g_fhi);
    cudaGetSymbolAddress((void**)&flo,  g_flo);
    cudaGetSymbolAddress((void**)&wThi, g_wThi);
    cudaGetSymbolAddress((void**)&wTlo, g_wTlo);
    cudaGetSymbolAddress((void**)&qkh,  g_qkvh);
    cudaGetSymbolAddress((void**)&qkl,  g_qkvl);

    cudaFuncSetAttribute(gemm_mma<128, 0, 0, 1, 0>, cudaFuncAttributeMaxDynamicSharedMemorySize, SMEM_BM128);
    cudaFuncSetAttribute(gemm_mma<128, 1, 0, 1, 0>, cudaFuncAttributeMaxDynamicSharedMemorySize, SMEM_BM128);
    cudaFuncSetAttribute(gemm_mma<64, 0, 0, 0, 0>,  cudaFuncAttributeMaxDynamicSharedMemorySize, SMEM_BM64);
    cudaFuncSetAttribute(gemm_mma<64, 0, 1, 0, 0>,  cudaFuncAttributeMaxDynamicSharedMemorySize, SMEM_BM64);
    cudaFuncSetAttribute(gemm_mma<64, 0, 1, 0, 1>,  cudaFuncAttributeMaxDynamicSharedMemorySize, SMEM_BM64);
    cudaFuncSetAttribute(attn_mma, cudaFuncAttributeMaxDynamicSharedMemorySize, ATT_SMEM);

    tr_all<<<dim3(32, 32, 25), dim3(32, 8)>>>(enc_W2, Wqkv, Wo, Wff1, Wff2, wThi, wTlo);

    build_zin_kernel<<<32, 256>>>(xc, yc, xt, zin);
    enc1_kernel<<<dim3(DMODEL / 64, T_TOTAL / 128), 256>>>(zin, enc_W1, enc_b1, ahi, alo);
    gemm_mma<64, 0, 0, 0, 0><<<dim3(2, 128), 256, SMEM_BM64>>>(
        ahi, alo, wThi, wTlo, enc_b2, zb, nullptr, nullptr, nullptr, 256, 256);

    for (int l = 0; l < LAYERS; l++) {
        size_t base = 65536 + (size_t)l * 786432;
        ln_kernel<<<T_TOTAL / 8, 256>>>(zb, ln1_g + l * DMODEL, ln1_b + l * DMODEL, ahi, alo);
        gemm_mma<128, 0, 0, 1, 0><<<dim3(6, 64), 256, SMEM_BM128>>>(
            ahi, alo, wThi + base, wTlo + base, bqkv + l * 768,
            nullptr, qkh, qkl, nullptr, 768, 256);
        attn_mma<<<dim3(8, 8, 8), 256, ATT_SMEM>>>(qkh, qkl, ahi, alo);
        gemm_mma<64, 0, 1, 0, 0><<<dim3(2, 128), 256, SMEM_BM64>>>(
            ahi, alo, wThi + base + 196608, wTlo + base + 196608, bo + l * DMODEL,
            zb, nullptr, nullptr, nullptr, 256, 256);
        ln_kernel<<<T_TOTAL / 8, 256>>>(zb, ln2_g + l * DMODEL, ln2_b + l * DMODEL, ahi, alo);
        gemm_mma<128, 1, 0, 1, 0><<<dim3(8, 64), 256, SMEM_BM128>>>(
            ahi, alo, wThi + base + 262144, wTlo + base + 262144, bff1 + l * FFDIM,
            nullptr, fhi, flo, nullptr, 1024, 256);
        if (l < LAYERS - 1) {
            gemm_mma<64, 0, 1, 0, 0><<<dim3(2, 128), 256, SMEM_BM64>>>(
                fhi, flo, wThi + base + 524288, wTlo + base + 524288, bff2 + l * DMODEL,
                zb, nullptr, nullptr, nullptr, 256, 1024);
        } else {
            gemm_mma<64, 0, 1, 0, 1><<<dim3(2, 128), 256, SMEM_BM64>>>(
                fhi, flo, wThi + base + 524288, wTlo + base + 524288, bff2 + l * DMODEL,
                zb, nullptr, nullptr, (float*)d_out, 256, 1024);
        }
    }
}